// round 11
// baseline (speedup 1.0000x reference)
#include <cuda_runtime.h>
#include <cuda_bf16.h>
#include <cstdint>

#define N_NODES 100000
#define N_EDGES 1600000

// ---------------- scratch (static device globals; no allocations) ----------------
__device__ int                g_is64;
__device__ unsigned long long g_degcnt[N_NODES];   // [63:44]=count, [43:0]=sum(ew)*2^32 (zeroed in k_scan)
__device__ float              g_dis[N_NODES];
__device__ int                g_rowptr[N_NODES + 1];
__device__ int                g_cursor[N_NODES];
__device__ int                g_colidx[N_EDGES];
__device__ float              g_enorm[N_EDGES];
__device__ float              g_bufA[(size_t)N_NODES * 128];
__device__ float              g_bufB[(size_t)N_NODES * 128];
// bf16 W fragments (hi/lo), packed bf16x2 words: W1@0 (8192), W2@8192, W3@16384 (4096)
__device__ unsigned g_wfh[20480];
__device__ unsigned g_wfl[20480];

__device__ __forceinline__ unsigned bf16pack(float a, float b) {
    unsigned short ha = __bfloat16_as_ushort(__float2bfloat16(a));
    unsigned short hb = __bfloat16_as_ushort(__float2bfloat16(b));
    return (unsigned)ha | ((unsigned)hb << 16);
}

// ---------------- dtype detection (int64 vs int32 edge_index) ----------------
__global__ void k_detect(const int* __restrict__ w) {
    __shared__ int any;
    if (threadIdx.x == 0) any = 0;
    __syncthreads();
    const int STRIDE = N_EDGES / 4096;
    for (int t = threadIdx.x; t < 4096; t += blockDim.x) {
        int v = w[2 * (t * STRIDE) + 1];
        if (v != 0) any = 1;
    }
    __syncthreads();
    if (threadIdx.x == 0) g_is64 = any ? 0 : 1;
}

__device__ __forceinline__ int load_idx(const void* ei, long long pos) {
    if (g_is64) return (int)((const long long*)ei)[pos];
    return ((const int*)ei)[pos];
}

// ---------------- prep kernels ----------------
__global__ void k_deg(const void* __restrict__ ei, const float* __restrict__ ew) {
    int e = blockIdx.x * blockDim.x + threadIdx.x;
    if (e < N_EDGES) {
        int dst = load_idx(ei, (long long)N_EDGES + e);
        unsigned long long p = (1ull << 44) | (unsigned long long)(ew[e] * 4294967296.0f);
        atomicAdd(&g_degcnt[dst], p);
    }
}

// prefix-scan counts -> rowptr/cursor; decode deg -> dis; zero degcnt for next replay
__global__ void k_scan() {
    __shared__ int sbuf[2][1024];
    const int tid = threadIdx.x;
    const int per = (N_NODES + 1023) / 1024;
    int start = tid * per;
    int end   = min(start + per, N_NODES);

    int s = 0;
    for (int i = start; i < end; i++) s += (int)(g_degcnt[i] >> 44);

    int sel = 0;
    sbuf[0][tid] = s;
    __syncthreads();
    for (int off = 1; off < 1024; off <<= 1) {
        int v = sbuf[sel][tid];
        if (tid >= off) v += sbuf[sel][tid - off];
        sbuf[sel ^ 1][tid] = v;
        sel ^= 1;
        __syncthreads();
    }
    int incl = sbuf[sel][tid];
    int run  = incl - s;
    for (int i = start; i < end; i++) {
        unsigned long long v = g_degcnt[i];
        g_degcnt[i] = 0ull;                     // reset for next graph replay
        int   c   = (int)(v >> 44);
        float deg = (float)(v & 0xFFFFFFFFFFFull) * (1.0f / 4294967296.0f) + 1.0f;
        g_dis[i] = rsqrtf(deg);
        g_rowptr[i] = run;
        g_cursor[i] = run;
        run += c;
    }
    if (end == N_NODES) g_rowptr[N_NODES] = run;
}

__global__ void k_scatter(const void* __restrict__ ei, const float* __restrict__ ew) {
    int e = blockIdx.x * blockDim.x + threadIdx.x;
    if (e < N_EDGES) {
        int src = load_idx(ei, e);
        int dst = load_idx(ei, (long long)N_EDGES + e);
        int p = atomicAdd(&g_cursor[dst], 1);
        g_colidx[p] = src;
        g_enorm[p]  = g_dis[src] * ew[e] * g_dis[dst];
    }
}

// ---------------- W fragment rearrangement (bf16 hi/lo, all 3 weights) ----------------
template <int N>
__device__ __forceinline__ void wfrag_body(const float* __restrict__ W,
                                           unsigned* __restrict__ outh,
                                           unsigned* __restrict__ outl, int blk) {
    constexpr int NT = N / 8;
    int tid = blk * 256 + threadIdx.x;
    if (tid >= 8 * NT * 32) return;
    int lane = tid & 31;
    int idx  = tid >> 5;
    int nt   = idx % NT;
    int ks   = idx / NT;
    int k0   = ks * 16 + (lane & 3) * 2;
    int n    = nt * 8 + (lane >> 2);
    float v[4] = { W[k0 * N + n], W[(k0 + 1) * N + n],
                   W[(k0 + 8) * N + n], W[(k0 + 9) * N + n] };
    float h[4], l[4];
    #pragma unroll
    for (int i = 0; i < 4; i++) {
        h[i] = __bfloat162float(__float2bfloat16(v[i]));
        l[i] = v[i] - h[i];
    }
    outh[tid * 2 + 0] = bf16pack(h[0], h[1]);
    outh[tid * 2 + 1] = bf16pack(h[2], h[3]);
    outl[tid * 2 + 0] = bf16pack(l[0], l[1]);
    outl[tid * 2 + 1] = bf16pack(l[2], l[3]);
}

__global__ void k_wfrag_all(const float* __restrict__ W1, const float* __restrict__ W2,
                            const float* __restrict__ W3) {
    int b = blockIdx.x;
    if (b < 16)      wfrag_body<128>(W1, g_wfh,         g_wfl,         b);
    else if (b < 32) wfrag_body<128>(W2, g_wfh + 8192,  g_wfl + 8192,  b - 16);
    else             wfrag_body<64>(W3,  g_wfh + 16384, g_wfl + 16384, b - 32);
}

// ---------------- tensor-core GEMM: Y[M,N] = X[M,128] @ W[128,N], 3xBF16 ----------------
#define MMA_BF16(D, A, B)                                                      \
    asm volatile(                                                              \
        "mma.sync.aligned.m16n8k16.row.col.f32.bf16.bf16.f32 "                 \
        "{%0,%1,%2,%3},{%4,%5,%6,%7},{%8,%9},{%0,%1,%2,%3};\n"                 \
        : "+f"(D[0]), "+f"(D[1]), "+f"(D[2]), "+f"(D[3])                       \
        : "r"(A[0]), "r"(A[1]), "r"(A[2]), "r"(A[3]), "r"(B[0]), "r"(B[1]))

template <int N>
__global__ void __launch_bounds__(256, 2)
k_gemm_tc(const float* __restrict__ X, const unsigned* __restrict__ Wh,
          const unsigned* __restrict__ Wl, float* __restrict__ Y) {
    constexpr int KC = 8;
    constexpr int NT = N / 8;
    constexpr int WN = N / 32;
    constexpr int MT = WN / 2;
    constexpr int BM = 64;
    constexpr int XROWW = 68;                    // bf16x2 words per row (64 + 4 pad)
    constexpr int XSZ = BM * XROWW;
    constexpr int PF = 8;

    extern __shared__ unsigned smu[];
    unsigned* xs_h = smu;
    unsigned* xs_l = smu + XSZ;

    const int tid = threadIdx.x, lane = tid & 31, wid = tid >> 5;
    const int wm = wid / WN, wn = wid % WN;
    const int NTILES = (N_NODES + BM - 1) / BM;

    int t = blockIdx.x;
    if (t < NTILES) {
        int r0 = t * BM;
        #pragma unroll
        for (int i = 0; i < PF; i++) {
            int f = tid + i * 256;
            int m = f >> 5, k4 = f & 31;
            int row = r0 + m;
            float4 v = make_float4(0.f, 0.f, 0.f, 0.f);
            if (row < N_NODES) v = ((const float4*)(X + (size_t)row * 128))[k4];
            float hx = __bfloat162float(__float2bfloat16(v.x));
            float hy = __bfloat162float(__float2bfloat16(v.y));
            float hz = __bfloat162float(__float2bfloat16(v.z));
            float hw = __bfloat162float(__float2bfloat16(v.w));
            xs_h[m * XROWW + k4 * 2 + 0] = bf16pack(hx, hy);
            xs_h[m * XROWW + k4 * 2 + 1] = bf16pack(hz, hw);
            xs_l[m * XROWW + k4 * 2 + 0] = bf16pack(v.x - hx, v.y - hy);
            xs_l[m * XROWW + k4 * 2 + 1] = bf16pack(v.z - hz, v.w - hw);
        }
    }
    __syncthreads();

    for (; t < NTILES; t += gridDim.x) {
        const int tn = t + gridDim.x;

        float4 pf[PF];
        if (tn < NTILES) {
            int r0 = tn * BM;
            #pragma unroll
            for (int i = 0; i < PF; i++) {
                int f = tid + i * 256;
                int m = f >> 5, k4 = f & 31;
                int row = r0 + m;
                pf[i] = make_float4(0.f, 0.f, 0.f, 0.f);
                if (row < N_NODES) pf[i] = ((const float4*)(X + (size_t)row * 128))[k4];
            }
        }

        float acc[MT][4][4];
        #pragma unroll
        for (int a = 0; a < MT; a++)
            #pragma unroll
            for (int b = 0; b < 4; b++)
                #pragma unroll
                for (int c = 0; c < 4; c++) acc[a][b][c] = 0.f;

        #pragma unroll
        for (int ks = 0; ks < KC; ks++) {
            const int p0 = ks * 8 + (lane & 3);
            unsigned ahi[MT][4], alo[MT][4];
            #pragma unroll
            for (int mt = 0; mt < MT; mt++) {
                int r = wm * (MT * 16) + mt * 16 + (lane >> 2);
                ahi[mt][0] = xs_h[r * XROWW + p0];
                ahi[mt][1] = xs_h[(r + 8) * XROWW + p0];
                ahi[mt][2] = xs_h[r * XROWW + p0 + 4];
                ahi[mt][3] = xs_h[(r + 8) * XROWW + p0 + 4];
                alo[mt][0] = xs_l[r * XROWW + p0];
                alo[mt][1] = xs_l[(r + 8) * XROWW + p0];
                alo[mt][2] = xs_l[r * XROWW + p0 + 4];
                alo[mt][3] = xs_l[(r + 8) * XROWW + p0 + 4];
            }
            unsigned bh[4][2], bl[4][2];
            #pragma unroll
            for (int j = 0; j < 4; j++) {
                int nt = wn * 4 + j;
                uint2 vh = __ldg((const uint2*)(Wh + ((size_t)(ks * NT + nt) * 32 + lane) * 2));
                uint2 vl = __ldg((const uint2*)(Wl + ((size_t)(ks * NT + nt) * 32 + lane) * 2));
                bh[j][0] = vh.x; bh[j][1] = vh.y;
                bl[j][0] = vl.x; bl[j][1] = vl.y;
            }
            #pragma unroll
            for (int mt = 0; mt < MT; mt++)
                #pragma unroll
                for (int j = 0; j < 4; j++) {
                    MMA_BF16(acc[mt][j], ahi[mt], bh[j]);
                    MMA_BF16(acc[mt][j], ahi[mt], bl[j]);
                    MMA_BF16(acc[mt][j], alo[mt], bh[j]);
                }
        }

        __syncthreads();
        if (tn < NTILES) {
            #pragma unroll
            for (int i = 0; i < PF; i++) {
                int f = tid + i * 256;
                int m = f >> 5, k4 = f & 31;
                float4 v = pf[i];
                float hx = __bfloat162float(__float2bfloat16(v.x));
                float hy = __bfloat162float(__float2bfloat16(v.y));
                float hz = __bfloat162float(__float2bfloat16(v.z));
                float hw = __bfloat162float(__float2bfloat16(v.w));
                xs_h[m * XROWW + k4 * 2 + 0] = bf16pack(hx, hy);
                xs_h[m * XROWW + k4 * 2 + 1] = bf16pack(hz, hw);
                xs_l[m * XROWW + k4 * 2 + 0] = bf16pack(v.x - hx, v.y - hy);
                xs_l[m * XROWW + k4 * 2 + 1] = bf16pack(v.z - hz, v.w - hw);
            }
        }
        __syncthreads();

        #pragma unroll
        for (int mt = 0; mt < MT; mt++) {
            int row = t * BM + wm * (MT * 16) + mt * 16 + (lane >> 2);
            #pragma unroll
            for (int j = 0; j < 4; j++) {
                int col = wn * 32 + j * 8 + (lane & 3) * 2;
                if (row < N_NODES)
                    *(float2*)(Y + (size_t)row * N + col) = make_float2(acc[mt][j][0], acc[mt][j][1]);
                if (row + 8 < N_NODES)
                    *(float2*)(Y + (size_t)(row + 8) * N + col) = make_float2(acc[mt][j][2], acc[mt][j][3]);
            }
        }
    }
}

// ---------------- aggregation: out[v] = sum_e norm*xw[src] + dis^2*xw[v] + b ----------------
template <bool RELU>
__global__ void k_agg128(const float* __restrict__ xw, const float* __restrict__ bias,
                         float* __restrict__ out) {
    int w = (blockIdx.x * blockDim.x + threadIdx.x) >> 5;
    int lane = threadIdx.x & 31;
    if (w >= N_NODES) return;

    int beg = g_rowptr[w], end = g_rowptr[w + 1];
    float4 acc = make_float4(0.f, 0.f, 0.f, 0.f);

    int e = beg;
    for (; e + 8 <= end; e += 8) {
        int s[8]; float n[8];
        #pragma unroll
        for (int u = 0; u < 8; u++) { s[u] = __ldg(&g_colidx[e + u]); n[u] = __ldg(&g_enorm[e + u]); }
        float4 t[8];
        #pragma unroll
        for (int u = 0; u < 8; u++)
            t[u] = __ldg(reinterpret_cast<const float4*>(xw + (size_t)s[u] * 128) + lane);
        #pragma unroll
        for (int u = 0; u < 8; u++) {
            acc.x = fmaf(n[u], t[u].x, acc.x);
            acc.y = fmaf(n[u], t[u].y, acc.y);
            acc.z = fmaf(n[u], t[u].z, acc.z);
            acc.w = fmaf(n[u], t[u].w, acc.w);
        }
    }
    for (; e < end; e++) {
        int   sc = __ldg(&g_colidx[e]);
        float nc = __ldg(&g_enorm[e]);
        float4 tc = __ldg(reinterpret_cast<const float4*>(xw + (size_t)sc * 128) + lane);
        acc.x = fmaf(nc, tc.x, acc.x);
        acc.y = fmaf(nc, tc.y, acc.y);
        acc.z = fmaf(nc, tc.z, acc.z);
        acc.w = fmaf(nc, tc.w, acc.w);
    }

    float d = g_dis[w];
    float self = d * d;
    float4 sv = __ldg(reinterpret_cast<const float4*>(xw + (size_t)w * 128) + lane);
    float4 bv = __ldg(reinterpret_cast<const float4*>(bias) + lane);
    acc.x = fmaf(self, sv.x, acc.x) + bv.x;
    acc.y = fmaf(self, sv.y, acc.y) + bv.y;
    acc.z = fmaf(self, sv.z, acc.z) + bv.z;
    acc.w = fmaf(self, sv.w, acc.w) + bv.w;
    if (RELU) {
        acc.x = fmaxf(acc.x, 0.f); acc.y = fmaxf(acc.y, 0.f);
        acc.z = fmaxf(acc.z, 0.f); acc.w = fmaxf(acc.w, 0.f);
    }
    *(reinterpret_cast<float4*>(out + (size_t)w * 128) + lane) = acc;
}

__global__ void k_agg64(const float* __restrict__ xw, const float* __restrict__ bias,
                        float* __restrict__ out) {
    int w = (blockIdx.x * blockDim.x + threadIdx.x) >> 5;
    int lane = threadIdx.x & 31;
    if (w >= N_NODES) return;

    int beg = g_rowptr[w], end = g_rowptr[w + 1];
    float2 acc = make_float2(0.f, 0.f);

    int e = beg;
    for (; e + 8 <= end; e += 8) {
        int s[8]; float n[8];
        #pragma unroll
        for (int u = 0; u < 8; u++) { s[u] = __ldg(&g_colidx[e + u]); n[u] = __ldg(&g_enorm[e + u]); }
        float2 t[8];
        #pragma unroll
        for (int u = 0; u < 8; u++)
            t[u] = __ldg(reinterpret_cast<const float2*>(xw + (size_t)s[u] * 64) + lane);
        #pragma unroll
        for (int u = 0; u < 8; u++) {
            acc.x = fmaf(n[u], t[u].x, acc.x);
            acc.y = fmaf(n[u], t[u].y, acc.y);
        }
    }
    for (; e < end; e++) {
        int   sc = __ldg(&g_colidx[e]);
        float nc = __ldg(&g_enorm[e]);
        float2 tc = __ldg(reinterpret_cast<const float2*>(xw + (size_t)sc * 64) + lane);
        acc.x = fmaf(nc, tc.x, acc.x);
        acc.y = fmaf(nc, tc.y, acc.y);
    }

    float d = g_dis[w];
    float self = d * d;
    float2 sv = __ldg(reinterpret_cast<const float2*>(xw + (size_t)w * 64) + lane);
    float2 bv = __ldg(reinterpret_cast<const float2*>(bias) + lane);
    acc.x = fmaf(self, sv.x, acc.x) + bv.x;
    acc.y = fmaf(self, sv.y, acc.y) + bv.y;
    *(reinterpret_cast<float2*>(out + (size_t)w * 64) + lane) = acc;
}

// ---------------- launch ----------------
extern "C" void kernel_launch(void* const* d_in, const int* in_sizes, int n_in,
                              void* d_out, int out_size) {
    const float* x  = (const float*)d_in[0];
    const void*  ei = d_in[1];
    const float* ew = (const float*)d_in[2];
    const float* W1 = (const float*)d_in[3];
    const float* b1 = (const float*)d_in[4];
    const float* W2 = (const float*)d_in[5];
    const float* b2 = (const float*)d_in[6];
    const float* W3 = (const float*)d_in[7];
    const float* b3 = (const float*)d_in[8];
    float* out = (float*)d_out;

    float*    bufA; cudaGetSymbolAddress((void**)&bufA, g_bufA);
    float*    bufB; cudaGetSymbolAddress((void**)&bufB, g_bufB);
    unsigned* wfh;  cudaGetSymbolAddress((void**)&wfh, g_wfh);
    unsigned* wfl;  cudaGetSymbolAddress((void**)&wfl, g_wfl);

    int nsm = 148;
    cudaDeviceGetAttribute(&nsm, cudaDevAttrMultiProcessorCount, 0);

    const int SMEM = 2 * 64 * 68 * 4;   // 34816 B (hi + lo X tile), 2 CTAs/SM
    cudaFuncSetAttribute(k_gemm_tc<128>, cudaFuncAttributeMaxDynamicSharedMemorySize, SMEM);
    cudaFuncSetAttribute(k_gemm_tc<64>,  cudaFuncAttributeMaxDynamicSharedMemorySize, SMEM);

    const int edgeBlocks = (N_EDGES + 255) / 256;
    const int aggBlocks  = (N_NODES + 7) / 8;

    // launch order: slot #4 (ncu's fixed window) = k_scan (last unmeasured bucket)
    k_detect<<<1, 256>>>((const int*)ei);                          // 1
    k_deg<<<edgeBlocks, 256>>>(ei, ew);                            // 2
    k_wfrag_all<<<40, 256>>>(W1, W2, W3);                          // 3
    k_scan<<<1, 1024>>>();                                         // 4  <- profiled
    k_gemm_tc<128><<<2 * nsm, 256, SMEM>>>(x, wfh, wfl, bufA);     // 5
    k_scatter<<<edgeBlocks, 256>>>(ei, ew);                        // 6
    k_agg128<true><<<aggBlocks, 256>>>(bufA, b1, bufB);            // 7
    k_gemm_tc<128><<<2 * nsm, 256, SMEM>>>(bufB, wfh + 8192, wfl + 8192, bufA);   // 8
    k_agg128<true><<<aggBlocks, 256>>>(bufA, b2, bufB);            // 9
    k_gemm_tc<64><<<2 * nsm, 256, SMEM>>>(bufB, wfh + 16384, wfl + 16384, bufA);  // 10
    k_agg64<<<aggBlocks, 256>>>(bufA, b3, out);                    // 11
}

// round 12
// speedup vs baseline: 1.8749x; 1.8749x over previous
#include <cuda_runtime.h>
#include <cuda_bf16.h>
#include <cstdint>

#define N_NODES 100000
#define N_EDGES 1600000
#define SCAN_BLOCKS 98   // ceil(N_NODES / 1024)

// ---------------- scratch (static device globals; no allocations) ----------------
__device__ int                g_is64;
__device__ unsigned long long g_degcnt[N_NODES];   // [63:44]=count, [43:0]=sum(ew)*2^32 (zeroed in k_scan3)
__device__ float              g_dis[N_NODES];
__device__ int                g_blocksum[SCAN_BLOCKS];
__device__ int                g_rowptr[N_NODES + 1];
__device__ int                g_cursor[N_NODES];
__device__ int                g_colidx[N_EDGES];
__device__ float              g_enorm[N_EDGES];
__device__ float              g_bufA[(size_t)N_NODES * 128];
__device__ float              g_bufB[(size_t)N_NODES * 128];
// bf16 W fragments (hi/lo), packed bf16x2 words: W1@0 (8192), W2@8192, W3@16384 (4096)
__device__ unsigned g_wfh[20480];
__device__ unsigned g_wfl[20480];

__device__ __forceinline__ unsigned bf16pack(float a, float b) {
    unsigned short ha = __bfloat16_as_ushort(__float2bfloat16(a));
    unsigned short hb = __bfloat16_as_ushort(__float2bfloat16(b));
    return (unsigned)ha | ((unsigned)hb << 16);
}

// ---------------- dtype detection (int64 vs int32 edge_index) ----------------
__global__ void k_detect(const int* __restrict__ w) {
    __shared__ int any;
    if (threadIdx.x == 0) any = 0;
    __syncthreads();
    const int STRIDE = N_EDGES / 4096;
    for (int t = threadIdx.x; t < 4096; t += blockDim.x) {
        int v = w[2 * (t * STRIDE) + 1];
        if (v != 0) any = 1;
    }
    __syncthreads();
    if (threadIdx.x == 0) g_is64 = any ? 0 : 1;
}

__device__ __forceinline__ int load_idx(const void* ei, long long pos) {
    if (g_is64) return (int)((const long long*)ei)[pos];
    return ((const int*)ei)[pos];
}

// ---------------- prep kernels ----------------
__global__ void k_deg(const void* __restrict__ ei, const float* __restrict__ ew) {
    int e = blockIdx.x * blockDim.x + threadIdx.x;
    if (e < N_EDGES) {
        int dst = load_idx(ei, (long long)N_EDGES + e);
        unsigned long long p = (1ull << 44) | (unsigned long long)(ew[e] * 4294967296.0f);
        atomicAdd(&g_degcnt[dst], p);
    }
}

// ---- parallel 3-phase scan ----
__global__ void k_scan1() {
    __shared__ int sdata[1024];
    int i = blockIdx.x * 1024 + threadIdx.x;
    int c = (i < N_NODES) ? (int)(g_degcnt[i] >> 44) : 0;
    sdata[threadIdx.x] = c;
    __syncthreads();
    for (int off = 512; off > 0; off >>= 1) {
        if (threadIdx.x < off) sdata[threadIdx.x] += sdata[threadIdx.x + off];
        __syncthreads();
    }
    if (threadIdx.x == 0) g_blocksum[blockIdx.x] = sdata[0];
}

__global__ void k_scan2() {
    __shared__ int sbuf[2][128];
    int tid = threadIdx.x;
    int v = (tid < SCAN_BLOCKS) ? g_blocksum[tid] : 0;
    int sel = 0;
    sbuf[0][tid] = v;
    __syncthreads();
    for (int off = 1; off < 128; off <<= 1) {
        int t = sbuf[sel][tid];
        if (tid >= off) t += sbuf[sel][tid - off];
        sbuf[sel ^ 1][tid] = t;
        sel ^= 1;
        __syncthreads();
    }
    if (tid < SCAN_BLOCKS) g_blocksum[tid] = sbuf[sel][tid] - v;   // exclusive
    if (tid == 0) g_rowptr[N_NODES] = N_EDGES;
}

__global__ void k_scan3() {
    __shared__ int sbuf[2][1024];
    int tid = threadIdx.x;
    int i = blockIdx.x * 1024 + tid;
    unsigned long long v = (i < N_NODES) ? g_degcnt[i] : 0ull;
    int c = (int)(v >> 44);
    int sel = 0;
    sbuf[0][tid] = c;
    __syncthreads();
    for (int off = 1; off < 1024; off <<= 1) {
        int t = sbuf[sel][tid];
        if (tid >= off) t += sbuf[sel][tid - off];
        sbuf[sel ^ 1][tid] = t;
        sel ^= 1;
        __syncthreads();
    }
    if (i < N_NODES) {
        int pos = g_blocksum[blockIdx.x] + sbuf[sel][tid] - c;     // exclusive
        g_rowptr[i] = pos;
        g_cursor[i] = pos;
        float deg = (float)(v & 0xFFFFFFFFFFFull) * (1.0f / 4294967296.0f) + 1.0f;
        g_dis[i] = rsqrtf(deg);
        g_degcnt[i] = 0ull;                      // reset for next graph replay
    }
}

__global__ void k_scatter(const void* __restrict__ ei, const float* __restrict__ ew) {
    int e = blockIdx.x * blockDim.x + threadIdx.x;
    if (e < N_EDGES) {
        int src = load_idx(ei, e);
        int dst = load_idx(ei, (long long)N_EDGES + e);
        int p = atomicAdd(&g_cursor[dst], 1);
        g_colidx[p] = src;
        g_enorm[p]  = g_dis[src] * ew[e] * g_dis[dst];
    }
}

// ---------------- W fragment rearrangement (bf16 hi/lo, all 3 weights) ----------------
template <int N>
__device__ __forceinline__ void wfrag_body(const float* __restrict__ W,
                                           unsigned* __restrict__ outh,
                                           unsigned* __restrict__ outl, int blk) {
    constexpr int NT = N / 8;
    int tid = blk * 256 + threadIdx.x;
    if (tid >= 8 * NT * 32) return;
    int lane = tid & 31;
    int idx  = tid >> 5;
    int nt   = idx % NT;
    int ks   = idx / NT;
    int k0   = ks * 16 + (lane & 3) * 2;
    int n    = nt * 8 + (lane >> 2);
    float v[4] = { W[k0 * N + n], W[(k0 + 1) * N + n],
                   W[(k0 + 8) * N + n], W[(k0 + 9) * N + n] };
    float h[4], l[4];
    #pragma unroll
    for (int i = 0; i < 4; i++) {
        h[i] = __bfloat162float(__float2bfloat16(v[i]));
        l[i] = v[i] - h[i];
    }
    outh[tid * 2 + 0] = bf16pack(h[0], h[1]);
    outh[tid * 2 + 1] = bf16pack(h[2], h[3]);
    outl[tid * 2 + 0] = bf16pack(l[0], l[1]);
    outl[tid * 2 + 1] = bf16pack(l[2], l[3]);
}

__global__ void k_wfrag_all(const float* __restrict__ W1, const float* __restrict__ W2,
                            const float* __restrict__ W3) {
    int b = blockIdx.x;
    if (b < 16)      wfrag_body<128>(W1, g_wfh,         g_wfl,         b);
    else if (b < 32) wfrag_body<128>(W2, g_wfh + 8192,  g_wfl + 8192,  b - 16);
    else             wfrag_body<64>(W3,  g_wfh + 16384, g_wfl + 16384, b - 32);
}

// ---------------- tensor-core GEMM: Y[M,N] = X[M,128] @ W[128,N], 3xBF16 ----------------
#define MMA_BF16(D, A, B)                                                      \
    asm volatile(                                                              \
        "mma.sync.aligned.m16n8k16.row.col.f32.bf16.bf16.f32 "                 \
        "{%0,%1,%2,%3},{%4,%5,%6,%7},{%8,%9},{%0,%1,%2,%3};\n"                 \
        : "+f"(D[0]), "+f"(D[1]), "+f"(D[2]), "+f"(D[3])                       \
        : "r"(A[0]), "r"(A[1]), "r"(A[2]), "r"(A[3]), "r"(B[0]), "r"(B[1]))

template <int N>
__global__ void __launch_bounds__(256, 2)
k_gemm_tc(const float* __restrict__ X, const unsigned* __restrict__ Wh,
          const unsigned* __restrict__ Wl, float* __restrict__ Y) {
    constexpr int KC = 8;
    constexpr int NT = N / 8;
    constexpr int WN = N / 32;
    constexpr int MT = WN / 2;
    constexpr int BM = 64;
    constexpr int XROWW = 68;
    constexpr int XSZ = BM * XROWW;
    constexpr int PF = 8;

    extern __shared__ unsigned smu[];
    unsigned* xs_h = smu;
    unsigned* xs_l = smu + XSZ;

    const int tid = threadIdx.x, lane = tid & 31, wid = tid >> 5;
    const int wm = wid / WN, wn = wid % WN;
    const int NTILES = (N_NODES + BM - 1) / BM;

    int t = blockIdx.x;
    if (t < NTILES) {
        int r0 = t * BM;
        #pragma unroll
        for (int i = 0; i < PF; i++) {
            int f = tid + i * 256;
            int m = f >> 5, k4 = f & 31;
            int row = r0 + m;
            float4 v = make_float4(0.f, 0.f, 0.f, 0.f);
            if (row < N_NODES) v = ((const float4*)(X + (size_t)row * 128))[k4];
            float hx = __bfloat162float(__float2bfloat16(v.x));
            float hy = __bfloat162float(__float2bfloat16(v.y));
            float hz = __bfloat162float(__float2bfloat16(v.z));
            float hw = __bfloat162float(__float2bfloat16(v.w));
            xs_h[m * XROWW + k4 * 2 + 0] = bf16pack(hx, hy);
            xs_h[m * XROWW + k4 * 2 + 1] = bf16pack(hz, hw);
            xs_l[m * XROWW + k4 * 2 + 0] = bf16pack(v.x - hx, v.y - hy);
            xs_l[m * XROWW + k4 * 2 + 1] = bf16pack(v.z - hz, v.w - hw);
        }
    }
    __syncthreads();

    for (; t < NTILES; t += gridDim.x) {
        const int tn = t + gridDim.x;

        float4 pf[PF];
        if (tn < NTILES) {
            int r0 = tn * BM;
            #pragma unroll
            for (int i = 0; i < PF; i++) {
                int f = tid + i * 256;
                int m = f >> 5, k4 = f & 31;
                int row = r0 + m;
                pf[i] = make_float4(0.f, 0.f, 0.f, 0.f);
                if (row < N_NODES) pf[i] = ((const float4*)(X + (size_t)row * 128))[k4];
            }
        }

        float acc[MT][4][4];
        #pragma unroll
        for (int a = 0; a < MT; a++)
            #pragma unroll
            for (int b = 0; b < 4; b++)
                #pragma unroll
                for (int c = 0; c < 4; c++) acc[a][b][c] = 0.f;

        #pragma unroll
        for (int ks = 0; ks < KC; ks++) {
            const int p0 = ks * 8 + (lane & 3);
            unsigned ahi[MT][4], alo[MT][4];
            #pragma unroll
            for (int mt = 0; mt < MT; mt++) {
                int r = wm * (MT * 16) + mt * 16 + (lane >> 2);
                ahi[mt][0] = xs_h[r * XROWW + p0];
                ahi[mt][1] = xs_h[(r + 8) * XROWW + p0];
                ahi[mt][2] = xs_h[r * XROWW + p0 + 4];
                ahi[mt][3] = xs_h[(r + 8) * XROWW + p0 + 4];
                alo[mt][0] = xs_l[r * XROWW + p0];
                alo[mt][1] = xs_l[(r + 8) * XROWW + p0];
                alo[mt][2] = xs_l[r * XROWW + p0 + 4];
                alo[mt][3] = xs_l[(r + 8) * XROWW + p0 + 4];
            }
            unsigned bh[4][2], bl[4][2];
            #pragma unroll
            for (int j = 0; j < 4; j++) {
                int nt = wn * 4 + j;
                uint2 vh = __ldg((const uint2*)(Wh + ((size_t)(ks * NT + nt) * 32 + lane) * 2));
                uint2 vl = __ldg((const uint2*)(Wl + ((size_t)(ks * NT + nt) * 32 + lane) * 2));
                bh[j][0] = vh.x; bh[j][1] = vh.y;
                bl[j][0] = vl.x; bl[j][1] = vl.y;
            }
            #pragma unroll
            for (int mt = 0; mt < MT; mt++)
                #pragma unroll
                for (int j = 0; j < 4; j++) {
                    MMA_BF16(acc[mt][j], ahi[mt], bh[j]);
                    MMA_BF16(acc[mt][j], ahi[mt], bl[j]);
                    MMA_BF16(acc[mt][j], alo[mt], bh[j]);
                }
        }

        __syncthreads();
        if (tn < NTILES) {
            #pragma unroll
            for (int i = 0; i < PF; i++) {
                int f = tid + i * 256;
                int m = f >> 5, k4 = f & 31;
                float4 v = pf[i];
                float hx = __bfloat162float(__float2bfloat16(v.x));
                float hy = __bfloat162float(__float2bfloat16(v.y));
                float hz = __bfloat162float(__float2bfloat16(v.z));
                float hw = __bfloat162float(__float2bfloat16(v.w));
                xs_h[m * XROWW + k4 * 2 + 0] = bf16pack(hx, hy);
                xs_h[m * XROWW + k4 * 2 + 1] = bf16pack(hz, hw);
                xs_l[m * XROWW + k4 * 2 + 0] = bf16pack(v.x - hx, v.y - hy);
                xs_l[m * XROWW + k4 * 2 + 1] = bf16pack(v.z - hz, v.w - hw);
            }
        }
        __syncthreads();

        #pragma unroll
        for (int mt = 0; mt < MT; mt++) {
            int row = t * BM + wm * (MT * 16) + mt * 16 + (lane >> 2);
            #pragma unroll
            for (int j = 0; j < 4; j++) {
                int col = wn * 32 + j * 8 + (lane & 3) * 2;
                if (row < N_NODES)
                    *(float2*)(Y + (size_t)row * N + col) = make_float2(acc[mt][j][0], acc[mt][j][1]);
                if (row + 8 < N_NODES)
                    *(float2*)(Y + (size_t)(row + 8) * N + col) = make_float2(acc[mt][j][2], acc[mt][j][3]);
            }
        }
    }
}

// ---------------- aggregation: out[v] = sum_e norm*xw[src] + dis^2*xw[v] + b ----------------
template <bool RELU>
__global__ void k_agg128(const float* __restrict__ xw, const float* __restrict__ bias,
                         float* __restrict__ out) {
    int w = (blockIdx.x * blockDim.x + threadIdx.x) >> 5;
    int lane = threadIdx.x & 31;
    if (w >= N_NODES) return;

    int beg = g_rowptr[w], end = g_rowptr[w + 1];
    float4 acc = make_float4(0.f, 0.f, 0.f, 0.f);

    int e = beg;
    for (; e + 8 <= end; e += 8) {
        int s[8]; float n[8];
        #pragma unroll
        for (int u = 0; u < 8; u++) { s[u] = __ldg(&g_colidx[e + u]); n[u] = __ldg(&g_enorm[e + u]); }
        float4 t[8];
        #pragma unroll
        for (int u = 0; u < 8; u++)
            t[u] = __ldg(reinterpret_cast<const float4*>(xw + (size_t)s[u] * 128) + lane);
        #pragma unroll
        for (int u = 0; u < 8; u++) {
            acc.x = fmaf(n[u], t[u].x, acc.x);
            acc.y = fmaf(n[u], t[u].y, acc.y);
            acc.z = fmaf(n[u], t[u].z, acc.z);
            acc.w = fmaf(n[u], t[u].w, acc.w);
        }
    }
    for (; e < end; e++) {
        int   sc = __ldg(&g_colidx[e]);
        float nc = __ldg(&g_enorm[e]);
        float4 tc = __ldg(reinterpret_cast<const float4*>(xw + (size_t)sc * 128) + lane);
        acc.x = fmaf(nc, tc.x, acc.x);
        acc.y = fmaf(nc, tc.y, acc.y);
        acc.z = fmaf(nc, tc.z, acc.z);
        acc.w = fmaf(nc, tc.w, acc.w);
    }

    float d = g_dis[w];
    float self = d * d;
    float4 sv = __ldg(reinterpret_cast<const float4*>(xw + (size_t)w * 128) + lane);
    float4 bv = __ldg(reinterpret_cast<const float4*>(bias) + lane);
    acc.x = fmaf(self, sv.x, acc.x) + bv.x;
    acc.y = fmaf(self, sv.y, acc.y) + bv.y;
    acc.z = fmaf(self, sv.z, acc.z) + bv.z;
    acc.w = fmaf(self, sv.w, acc.w) + bv.w;
    if (RELU) {
        acc.x = fmaxf(acc.x, 0.f); acc.y = fmaxf(acc.y, 0.f);
        acc.z = fmaxf(acc.z, 0.f); acc.w = fmaxf(acc.w, 0.f);
    }
    *(reinterpret_cast<float4*>(out + (size_t)w * 128) + lane) = acc;
}

__global__ void k_agg64(const float* __restrict__ xw, const float* __restrict__ bias,
                        float* __restrict__ out) {
    int w = (blockIdx.x * blockDim.x + threadIdx.x) >> 5;
    int lane = threadIdx.x & 31;
    if (w >= N_NODES) return;

    int beg = g_rowptr[w], end = g_rowptr[w + 1];
    float2 acc = make_float2(0.f, 0.f);

    int e = beg;
    for (; e + 8 <= end; e += 8) {
        int s[8]; float n[8];
        #pragma unroll
        for (int u = 0; u < 8; u++) { s[u] = __ldg(&g_colidx[e + u]); n[u] = __ldg(&g_enorm[e + u]); }
        float2 t[8];
        #pragma unroll
        for (int u = 0; u < 8; u++)
            t[u] = __ldg(reinterpret_cast<const float2*>(xw + (size_t)s[u] * 64) + lane);
        #pragma unroll
        for (int u = 0; u < 8; u++) {
            acc.x = fmaf(n[u], t[u].x, acc.x);
            acc.y = fmaf(n[u], t[u].y, acc.y);
        }
    }
    for (; e < end; e++) {
        int   sc = __ldg(&g_colidx[e]);
        float nc = __ldg(&g_enorm[e]);
        float2 tc = __ldg(reinterpret_cast<const float2*>(xw + (size_t)sc * 64) + lane);
        acc.x = fmaf(nc, tc.x, acc.x);
        acc.y = fmaf(nc, tc.y, acc.y);
    }

    float d = g_dis[w];
    float self = d * d;
    float2 sv = __ldg(reinterpret_cast<const float2*>(xw + (size_t)w * 64) + lane);
    float2 bv = __ldg(reinterpret_cast<const float2*>(bias) + lane);
    acc.x = fmaf(self, sv.x, acc.x) + bv.x;
    acc.y = fmaf(self, sv.y, acc.y) + bv.y;
    *(reinterpret_cast<float2*>(out + (size_t)w * 64) + lane) = acc;
}

// ---------------- launch ----------------
extern "C" void kernel_launch(void* const* d_in, const int* in_sizes, int n_in,
                              void* d_out, int out_size) {
    const float* x  = (const float*)d_in[0];
    const void*  ei = d_in[1];
    const float* ew = (const float*)d_in[2];
    const float* W1 = (const float*)d_in[3];
    const float* b1 = (const float*)d_in[4];
    const float* W2 = (const float*)d_in[5];
    const float* b2 = (const float*)d_in[6];
    const float* W3 = (const float*)d_in[7];
    const float* b3 = (const float*)d_in[8];
    float* out = (float*)d_out;

    float*    bufA; cudaGetSymbolAddress((void**)&bufA, g_bufA);
    float*    bufB; cudaGetSymbolAddress((void**)&bufB, g_bufB);
    unsigned* wfh;  cudaGetSymbolAddress((void**)&wfh, g_wfh);
    unsigned* wfl;  cudaGetSymbolAddress((void**)&wfl, g_wfl);

    int nsm = 148;
    cudaDeviceGetAttribute(&nsm, cudaDevAttrMultiProcessorCount, 0);

    const int SMEM = 2 * 64 * 68 * 4;   // 34816 B (hi + lo X tile), 2 CTAs/SM
    cudaFuncSetAttribute(k_gemm_tc<128>, cudaFuncAttributeMaxDynamicSharedMemorySize, SMEM);
    cudaFuncSetAttribute(k_gemm_tc<64>,  cudaFuncAttributeMaxDynamicSharedMemorySize, SMEM);

    const int edgeBlocks = (N_EDGES + 255) / 256;
    const int aggBlocks  = (N_NODES + 7) / 8;

    // slot #4 (ncu's fixed window) = k_scan1 — verify the scan fix
    k_detect<<<1, 256>>>((const int*)ei);                          // 1
    k_deg<<<edgeBlocks, 256>>>(ei, ew);                            // 2
    k_wfrag_all<<<40, 256>>>(W1, W2, W3);                          // 3
    k_scan1<<<SCAN_BLOCKS, 1024>>>();                              // 4  <- profiled
    k_scan2<<<1, 128>>>();                                         // 5
    k_scan3<<<SCAN_BLOCKS, 1024>>>();                              // 6
    k_gemm_tc<128><<<2 * nsm, 256, SMEM>>>(x, wfh, wfl, bufA);     // 7
    k_scatter<<<edgeBlocks, 256>>>(ei, ew);                        // 8
    k_agg128<true><<<aggBlocks, 256>>>(bufA, b1, bufB);            // 9
    k_gemm_tc<128><<<2 * nsm, 256, SMEM>>>(bufB, wfh + 8192, wfl + 8192, bufA);   // 10
    k_agg128<true><<<aggBlocks, 256>>>(bufA, b2, bufB);            // 11
    k_gemm_tc<64><<<2 * nsm, 256, SMEM>>>(bufB, wfh + 16384, wfl + 16384, bufA);  // 12
    k_agg64<<<aggBlocks, 256>>>(bufA, b3, out);                    // 13
}

// round 13
// speedup vs baseline: 2.0904x; 1.1149x over previous
#include <cuda_runtime.h>
#include <cuda_fp16.h>
#include <cuda_bf16.h>
#include <cstdint>

#define N_NODES 100000
#define N_EDGES 1600000
#define SCAN_BLOCKS 98   // ceil(N_NODES / 1024)

// ---------------- scratch (static device globals; no allocations) ----------------
__device__ int                g_is64;
__device__ unsigned long long g_degcnt[N_NODES];   // [63:44]=count, [43:0]=sum(ew)*2^32 (zeroed in k_scan3)
__device__ float              g_dis[N_NODES];
__device__ int                g_blocksum[SCAN_BLOCKS];
__device__ int                g_rowptr[N_NODES + 1];
__device__ int                g_cursor[N_NODES];
__device__ int                g_colidx[N_EDGES];
__device__ float              g_enorm[N_EDGES];
__device__ __half             g_bufA[(size_t)N_NODES * 128];  // GEMM outputs (fp16 gather source)
__device__ float              g_bufB[(size_t)N_NODES * 128];  // relu(H) fp32
// bf16 W fragments (hi/lo), packed bf16x2 words: W1@0 (8192), W2@8192, W3@16384 (4096)
__device__ unsigned g_wfh[20480];
__device__ unsigned g_wfl[20480];

__device__ __forceinline__ unsigned bf16pack(float a, float b) {
    unsigned short ha = __bfloat16_as_ushort(__float2bfloat16(a));
    unsigned short hb = __bfloat16_as_ushort(__float2bfloat16(b));
    return (unsigned)ha | ((unsigned)hb << 16);
}

// ---------------- dtype detection (int64 vs int32 edge_index) ----------------
__global__ void k_detect(const int* __restrict__ w) {
    __shared__ int any;
    if (threadIdx.x == 0) any = 0;
    __syncthreads();
    const int STRIDE = N_EDGES / 4096;
    for (int t = threadIdx.x; t < 4096; t += blockDim.x) {
        int v = w[2 * (t * STRIDE) + 1];
        if (v != 0) any = 1;
    }
    __syncthreads();
    if (threadIdx.x == 0) g_is64 = any ? 0 : 1;
}

__device__ __forceinline__ int load_idx(const void* ei, long long pos) {
    if (g_is64) return (int)((const long long*)ei)[pos];
    return ((const int*)ei)[pos];
}

// ---------------- prep kernels ----------------
__global__ void k_deg(const void* __restrict__ ei, const float* __restrict__ ew) {
    int e = blockIdx.x * blockDim.x + threadIdx.x;
    if (e < N_EDGES) {
        int dst = load_idx(ei, (long long)N_EDGES + e);
        unsigned long long p = (1ull << 44) | (unsigned long long)(ew[e] * 4294967296.0f);
        atomicAdd(&g_degcnt[dst], p);
    }
}

// ---- parallel 3-phase scan ----
__global__ void k_scan1() {
    __shared__ int sdata[1024];
    int i = blockIdx.x * 1024 + threadIdx.x;
    int c = (i < N_NODES) ? (int)(g_degcnt[i] >> 44) : 0;
    sdata[threadIdx.x] = c;
    __syncthreads();
    for (int off = 512; off > 0; off >>= 1) {
        if (threadIdx.x < off) sdata[threadIdx.x] += sdata[threadIdx.x + off];
        __syncthreads();
    }
    if (threadIdx.x == 0) g_blocksum[blockIdx.x] = sdata[0];
}

__global__ void k_scan2() {
    __shared__ int sbuf[2][128];
    int tid = threadIdx.x;
    int v = (tid < SCAN_BLOCKS) ? g_blocksum[tid] : 0;
    int sel = 0;
    sbuf[0][tid] = v;
    __syncthreads();
    for (int off = 1; off < 128; off <<= 1) {
        int t = sbuf[sel][tid];
        if (tid >= off) t += sbuf[sel][tid - off];
        sbuf[sel ^ 1][tid] = t;
        sel ^= 1;
        __syncthreads();
    }
    if (tid < SCAN_BLOCKS) g_blocksum[tid] = sbuf[sel][tid] - v;   // exclusive
    if (tid == 0) g_rowptr[N_NODES] = N_EDGES;
}

__global__ void k_scan3() {
    __shared__ int sbuf[2][1024];
    int tid = threadIdx.x;
    int i = blockIdx.x * 1024 + tid;
    unsigned long long v = (i < N_NODES) ? g_degcnt[i] : 0ull;
    int c = (int)(v >> 44);
    int sel = 0;
    sbuf[0][tid] = c;
    __syncthreads();
    for (int off = 1; off < 1024; off <<= 1) {
        int t = sbuf[sel][tid];
        if (tid >= off) t += sbuf[sel][tid - off];
        sbuf[sel ^ 1][tid] = t;
        sel ^= 1;
        __syncthreads();
    }
    if (i < N_NODES) {
        int pos = g_blocksum[blockIdx.x] + sbuf[sel][tid] - c;     // exclusive
        g_rowptr[i] = pos;
        g_cursor[i] = pos;
        float deg = (float)(v & 0xFFFFFFFFFFFull) * (1.0f / 4294967296.0f) + 1.0f;
        g_dis[i] = rsqrtf(deg);
        g_degcnt[i] = 0ull;                      // reset for next graph replay
    }
}

__global__ void k_scatter(const void* __restrict__ ei, const float* __restrict__ ew) {
    int e = blockIdx.x * blockDim.x + threadIdx.x;
    if (e < N_EDGES) {
        int src = load_idx(ei, e);
        int dst = load_idx(ei, (long long)N_EDGES + e);
        int p = atomicAdd(&g_cursor[dst], 1);
        g_colidx[p] = src;
        g_enorm[p]  = g_dis[src] * ew[e] * g_dis[dst];
    }
}

// ---------------- W fragment rearrangement (bf16 hi/lo, all 3 weights) ----------------
template <int N>
__device__ __forceinline__ void wfrag_body(const float* __restrict__ W,
                                           unsigned* __restrict__ outh,
                                           unsigned* __restrict__ outl, int blk) {
    constexpr int NT = N / 8;
    int tid = blk * 256 + threadIdx.x;
    if (tid >= 8 * NT * 32) return;
    int lane = tid & 31;
    int idx  = tid >> 5;
    int nt   = idx % NT;
    int ks   = idx / NT;
    int k0   = ks * 16 + (lane & 3) * 2;
    int n    = nt * 8 + (lane >> 2);
    float v[4] = { W[k0 * N + n], W[(k0 + 1) * N + n],
                   W[(k0 + 8) * N + n], W[(k0 + 9) * N + n] };
    float h[4], l[4];
    #pragma unroll
    for (int i = 0; i < 4; i++) {
        h[i] = __bfloat162float(__float2bfloat16(v[i]));
        l[i] = v[i] - h[i];
    }
    outh[tid * 2 + 0] = bf16pack(h[0], h[1]);
    outh[tid * 2 + 1] = bf16pack(h[2], h[3]);
    outl[tid * 2 + 0] = bf16pack(l[0], l[1]);
    outl[tid * 2 + 1] = bf16pack(l[2], l[3]);
}

__global__ void k_wfrag_all(const float* __restrict__ W1, const float* __restrict__ W2,
                            const float* __restrict__ W3) {
    int b = blockIdx.x;
    if (b < 16)      wfrag_body<128>(W1, g_wfh,         g_wfl,         b);
    else if (b < 32) wfrag_body<128>(W2, g_wfh + 8192,  g_wfl + 8192,  b - 16);
    else             wfrag_body<64>(W3,  g_wfh + 16384, g_wfl + 16384, b - 32);
}

// ---------------- tensor-core GEMM: Y[M,N] = X[M,128] @ W[128,N], 3xBF16, fp16 out ----------------
#define MMA_BF16(D, A, B)                                                      \
    asm volatile(                                                              \
        "mma.sync.aligned.m16n8k16.row.col.f32.bf16.bf16.f32 "                 \
        "{%0,%1,%2,%3},{%4,%5,%6,%7},{%8,%9},{%0,%1,%2,%3};\n"                 \
        : "+f"(D[0]), "+f"(D[1]), "+f"(D[2]), "+f"(D[3])                       \
        : "r"(A[0]), "r"(A[1]), "r"(A[2]), "r"(A[3]), "r"(B[0]), "r"(B[1]))

template <int N>
__global__ void __launch_bounds__(256, 2)
k_gemm_tc(const float* __restrict__ X, const unsigned* __restrict__ Wh,
          const unsigned* __restrict__ Wl, __half* __restrict__ Y) {
    constexpr int KC = 8;
    constexpr int NT = N / 8;
    constexpr int WN = N / 32;
    constexpr int MT = WN / 2;
    constexpr int BM = 64;
    constexpr int XROWW = 68;
    constexpr int XSZ = BM * XROWW;
    constexpr int PF = 8;

    extern __shared__ unsigned smu[];
    unsigned* xs_h = smu;
    unsigned* xs_l = smu + XSZ;

    const int tid = threadIdx.x, lane = tid & 31, wid = tid >> 5;
    const int wm = wid / WN, wn = wid % WN;
    const int NTILES = (N_NODES + BM - 1) / BM;

    int t = blockIdx.x;
    if (t < NTILES) {
        int r0 = t * BM;
        #pragma unroll
        for (int i = 0; i < PF; i++) {
            int f = tid + i * 256;
            int m = f >> 5, k4 = f & 31;
            int row = r0 + m;
            float4 v = make_float4(0.f, 0.f, 0.f, 0.f);
            if (row < N_NODES) v = ((const float4*)(X + (size_t)row * 128))[k4];
            float hx = __bfloat162float(__float2bfloat16(v.x));
            float hy = __bfloat162float(__float2bfloat16(v.y));
            float hz = __bfloat162float(__float2bfloat16(v.z));
            float hw = __bfloat162float(__float2bfloat16(v.w));
            xs_h[m * XROWW + k4 * 2 + 0] = bf16pack(hx, hy);
            xs_h[m * XROWW + k4 * 2 + 1] = bf16pack(hz, hw);
            xs_l[m * XROWW + k4 * 2 + 0] = bf16pack(v.x - hx, v.y - hy);
            xs_l[m * XROWW + k4 * 2 + 1] = bf16pack(v.z - hz, v.w - hw);
        }
    }
    __syncthreads();

    for (; t < NTILES; t += gridDim.x) {
        const int tn = t + gridDim.x;

        float4 pf[PF];
        if (tn < NTILES) {
            int r0 = tn * BM;
            #pragma unroll
            for (int i = 0; i < PF; i++) {
                int f = tid + i * 256;
                int m = f >> 5, k4 = f & 31;
                int row = r0 + m;
                pf[i] = make_float4(0.f, 0.f, 0.f, 0.f);
                if (row < N_NODES) pf[i] = ((const float4*)(X + (size_t)row * 128))[k4];
            }
        }

        float acc[MT][4][4];
        #pragma unroll
        for (int a = 0; a < MT; a++)
            #pragma unroll
            for (int b = 0; b < 4; b++)
                #pragma unroll
                for (int c = 0; c < 4; c++) acc[a][b][c] = 0.f;

        #pragma unroll
        for (int ks = 0; ks < KC; ks++) {
            const int p0 = ks * 8 + (lane & 3);
            unsigned ahi[MT][4], alo[MT][4];
            #pragma unroll
            for (int mt = 0; mt < MT; mt++) {
                int r = wm * (MT * 16) + mt * 16 + (lane >> 2);
                ahi[mt][0] = xs_h[r * XROWW + p0];
                ahi[mt][1] = xs_h[(r + 8) * XROWW + p0];
                ahi[mt][2] = xs_h[r * XROWW + p0 + 4];
                ahi[mt][3] = xs_h[(r + 8) * XROWW + p0 + 4];
                alo[mt][0] = xs_l[r * XROWW + p0];
                alo[mt][1] = xs_l[(r + 8) * XROWW + p0];
                alo[mt][2] = xs_l[r * XROWW + p0 + 4];
                alo[mt][3] = xs_l[(r + 8) * XROWW + p0 + 4];
            }
            unsigned bh[4][2], bl[4][2];
            #pragma unroll
            for (int j = 0; j < 4; j++) {
                int nt = wn * 4 + j;
                uint2 vh = __ldg((const uint2*)(Wh + ((size_t)(ks * NT + nt) * 32 + lane) * 2));
                uint2 vl = __ldg((const uint2*)(Wl + ((size_t)(ks * NT + nt) * 32 + lane) * 2));
                bh[j][0] = vh.x; bh[j][1] = vh.y;
                bl[j][0] = vl.x; bl[j][1] = vl.y;
            }
            #pragma unroll
            for (int mt = 0; mt < MT; mt++)
                #pragma unroll
                for (int j = 0; j < 4; j++) {
                    MMA_BF16(acc[mt][j], ahi[mt], bh[j]);
                    MMA_BF16(acc[mt][j], ahi[mt], bl[j]);
                    MMA_BF16(acc[mt][j], alo[mt], bh[j]);
                }
        }

        __syncthreads();
        if (tn < NTILES) {
            #pragma unroll
            for (int i = 0; i < PF; i++) {
                int f = tid + i * 256;
                int m = f >> 5, k4 = f & 31;
                float4 v = pf[i];
                float hx = __bfloat162float(__float2bfloat16(v.x));
                float hy = __bfloat162float(__float2bfloat16(v.y));
                float hz = __bfloat162float(__float2bfloat16(v.z));
                float hw = __bfloat162float(__float2bfloat16(v.w));
                xs_h[m * XROWW + k4 * 2 + 0] = bf16pack(hx, hy);
                xs_h[m * XROWW + k4 * 2 + 1] = bf16pack(hz, hw);
                xs_l[m * XROWW + k4 * 2 + 0] = bf16pack(v.x - hx, v.y - hy);
                xs_l[m * XROWW + k4 * 2 + 1] = bf16pack(v.z - hz, v.w - hw);
            }
        }
        __syncthreads();

        // store output tile as fp16
        #pragma unroll
        for (int mt = 0; mt < MT; mt++) {
            int row = t * BM + wm * (MT * 16) + mt * 16 + (lane >> 2);
            #pragma unroll
            for (int j = 0; j < 4; j++) {
                int col = wn * 32 + j * 8 + (lane & 3) * 2;
                if (row < N_NODES)
                    *(__half2*)(Y + (size_t)row * N + col) =
                        __floats2half2_rn(acc[mt][j][0], acc[mt][j][1]);
                if (row + 8 < N_NODES)
                    *(__half2*)(Y + (size_t)(row + 8) * N + col) =
                        __floats2half2_rn(acc[mt][j][2], acc[mt][j][3]);
            }
        }
    }
}

// ---------------- aggregation (fp16 gather, fp32 accumulate) ----------------
template <bool RELU>
__global__ void k_agg128(const __half* __restrict__ xw, const float* __restrict__ bias,
                         float* __restrict__ out) {
    int w = (blockIdx.x * blockDim.x + threadIdx.x) >> 5;
    int lane = threadIdx.x & 31;
    if (w >= N_NODES) return;

    int beg = g_rowptr[w], end = g_rowptr[w + 1];
    float4 acc = make_float4(0.f, 0.f, 0.f, 0.f);

    int e = beg;
    for (; e + 8 <= end; e += 8) {
        int s[8]; float n[8];
        #pragma unroll
        for (int u = 0; u < 8; u++) { s[u] = __ldg(&g_colidx[e + u]); n[u] = __ldg(&g_enorm[e + u]); }
        uint2 t[8];
        #pragma unroll
        for (int u = 0; u < 8; u++)
            t[u] = __ldg(reinterpret_cast<const uint2*>(xw + (size_t)s[u] * 128) + lane);
        #pragma unroll
        for (int u = 0; u < 8; u++) {
            float2 f0 = __half22float2(*(__half2*)&t[u].x);
            float2 f1 = __half22float2(*(__half2*)&t[u].y);
            acc.x = fmaf(n[u], f0.x, acc.x);
            acc.y = fmaf(n[u], f0.y, acc.y);
            acc.z = fmaf(n[u], f1.x, acc.z);
            acc.w = fmaf(n[u], f1.y, acc.w);
        }
    }
    for (; e < end; e++) {
        int   sc = __ldg(&g_colidx[e]);
        float nc = __ldg(&g_enorm[e]);
        uint2 tc = __ldg(reinterpret_cast<const uint2*>(xw + (size_t)sc * 128) + lane);
        float2 f0 = __half22float2(*(__half2*)&tc.x);
        float2 f1 = __half22float2(*(__half2*)&tc.y);
        acc.x = fmaf(nc, f0.x, acc.x);
        acc.y = fmaf(nc, f0.y, acc.y);
        acc.z = fmaf(nc, f1.x, acc.z);
        acc.w = fmaf(nc, f1.y, acc.w);
    }

    float d = g_dis[w];
    float self = d * d;
    uint2 sr = __ldg(reinterpret_cast<const uint2*>(xw + (size_t)w * 128) + lane);
    float2 s0 = __half22float2(*(__half2*)&sr.x);
    float2 s1 = __half22float2(*(__half2*)&sr.y);
    float4 bv = __ldg(reinterpret_cast<const float4*>(bias) + lane);
    acc.x = fmaf(self, s0.x, acc.x) + bv.x;
    acc.y = fmaf(self, s0.y, acc.y) + bv.y;
    acc.z = fmaf(self, s1.x, acc.z) + bv.z;
    acc.w = fmaf(self, s1.y, acc.w) + bv.w;
    if (RELU) {
        acc.x = fmaxf(acc.x, 0.f); acc.y = fmaxf(acc.y, 0.f);
        acc.z = fmaxf(acc.z, 0.f); acc.w = fmaxf(acc.w, 0.f);
    }
    *(reinterpret_cast<float4*>(out + (size_t)w * 128) + lane) = acc;
}

__global__ void k_agg64(const __half* __restrict__ xw, const float* __restrict__ bias,
                        float* __restrict__ out) {
    int w = (blockIdx.x * blockDim.x + threadIdx.x) >> 5;
    int lane = threadIdx.x & 31;
    if (w >= N_NODES) return;

    int beg = g_rowptr[w], end = g_rowptr[w + 1];
    float2 acc = make_float2(0.f, 0.f);

    int e = beg;
    for (; e + 8 <= end; e += 8) {
        int s[8]; float n[8];
        #pragma unroll
        for (int u = 0; u < 8; u++) { s[u] = __ldg(&g_colidx[e + u]); n[u] = __ldg(&g_enorm[e + u]); }
        unsigned t[8];
        #pragma unroll
        for (int u = 0; u < 8; u++)
            t[u] = __ldg(reinterpret_cast<const unsigned*>(xw + (size_t)s[u] * 64) + lane);
        #pragma unroll
        for (int u = 0; u < 8; u++) {
            float2 f = __half22float2(*(__half2*)&t[u]);
            acc.x = fmaf(n[u], f.x, acc.x);
            acc.y = fmaf(n[u], f.y, acc.y);
        }
    }
    for (; e < end; e++) {
        int   sc = __ldg(&g_colidx[e]);
        float nc = __ldg(&g_enorm[e]);
        unsigned tc = __ldg(reinterpret_cast<const unsigned*>(xw + (size_t)sc * 64) + lane);
        float2 f = __half22float2(*(__half2*)&tc);
        acc.x = fmaf(nc, f.x, acc.x);
        acc.y = fmaf(nc, f.y, acc.y);
    }

    float d = g_dis[w];
    float self = d * d;
    unsigned sr = __ldg(reinterpret_cast<const unsigned*>(xw + (size_t)w * 64) + lane);
    float2 sf = __half22float2(*(__half2*)&sr);
    float2 bv = __ldg(reinterpret_cast<const float2*>(bias) + lane);
    acc.x = fmaf(self, sf.x, acc.x) + bv.x;
    acc.y = fmaf(self, sf.y, acc.y) + bv.y;
    *(reinterpret_cast<float2*>(out + (size_t)w * 64) + lane) = acc;
}

// ---------------- launch ----------------
extern "C" void kernel_launch(void* const* d_in, const int* in_sizes, int n_in,
                              void* d_out, int out_size) {
    const float* x  = (const float*)d_in[0];
    const void*  ei = d_in[1];
    const float* ew = (const float*)d_in[2];
    const float* W1 = (const float*)d_in[3];
    const float* b1 = (const float*)d_in[4];
    const float* W2 = (const float*)d_in[5];
    const float* b2 = (const float*)d_in[6];
    const float* W3 = (const float*)d_in[7];
    const float* b3 = (const float*)d_in[8];
    float* out = (float*)d_out;

    __half*   bufA; cudaGetSymbolAddress((void**)&bufA, g_bufA);
    float*    bufB; cudaGetSymbolAddress((void**)&bufB, g_bufB);
    unsigned* wfh;  cudaGetSymbolAddress((void**)&wfh, g_wfh);
    unsigned* wfl;  cudaGetSymbolAddress((void**)&wfl, g_wfl);

    int nsm = 148;
    cudaDeviceGetAttribute(&nsm, cudaDevAttrMultiProcessorCount, 0);

    const int SMEM = 2 * 64 * 68 * 4;   // 34816 B (hi + lo X tile), 2 CTAs/SM
    cudaFuncSetAttribute(k_gemm_tc<128>, cudaFuncAttributeMaxDynamicSharedMemorySize, SMEM);
    cudaFuncSetAttribute(k_gemm_tc<64>,  cudaFuncAttributeMaxDynamicSharedMemorySize, SMEM);

    const int edgeBlocks = (N_EDGES + 255) / 256;
    const int aggBlocks  = (N_NODES + 7) / 8;

    k_detect<<<1, 256>>>((const int*)ei);                          // 1
    k_deg<<<edgeBlocks, 256>>>(ei, ew);                            // 2
    k_wfrag_all<<<40, 256>>>(W1, W2, W3);                          // 3
    k_scan1<<<SCAN_BLOCKS, 1024>>>();                              // 4  <- profiled
    k_scan2<<<1, 128>>>();                                         // 5
    k_scan3<<<SCAN_BLOCKS, 1024>>>();                              // 6
    k_gemm_tc<128><<<2 * nsm, 256, SMEM>>>(x, wfh, wfl, bufA);     // 7
    k_scatter<<<edgeBlocks, 256>>>(ei, ew);                        // 8
    k_agg128<true><<<aggBlocks, 256>>>(bufA, b1, bufB);            // 9
    k_gemm_tc<128><<<2 * nsm, 256, SMEM>>>(bufB, wfh + 8192, wfl + 8192, bufA);   // 10
    k_agg128<true><<<aggBlocks, 256>>>(bufA, b2, bufB);            // 11
    k_gemm_tc<64><<<2 * nsm, 256, SMEM>>>(bufB, wfh + 16384, wfl + 16384, bufA);  // 12
    k_agg64<<<aggBlocks, 256>>>(bufA, b3, out);                    // 13
}